// round 1
// baseline (speedup 1.0000x reference)
#include <cuda_runtime.h>
#include <cstdint>

#define BB 32
#define AA 8400
#define NCH 84
#define NCC 80
#define KTOP 1500
#define TPAD 1536
#define SORTN 2048
#define MAXDET 300
#define NW 47
#define NWP 48

// ---------------- device scratch (static, allocation-free) ----------------
__device__ uint64_t g_keys[BB * AA];                 // sort keys (score|~idx)
__device__ int      g_cls[BB * AA];                  // argmax class per anchor
__device__ uint32_t g_cand[2][BB][AA];               // radix-select candidate lists
__device__ float4   g_selbox[BB * TPAD];             // original boxes of top-k
__device__ float4   g_nmsbox[BB * TPAD];             // class-offset scaled boxes
__device__ float    g_selscore[BB * TPAD];
__device__ float    g_selcls[BB * TPAD];
__device__ uint32_t g_validbits[BB * NWP];
__device__ uint32_t g_rownz[BB * NWP];
__device__ uint32_t g_mask[BB * KTOP * NWP];         // suppression bitmask rows

// orderable float -> uint (monotonic)
__device__ __forceinline__ uint32_t f2o(float f) {
    uint32_t u = __float_as_uint(f);
    return (u & 0x80000000u) ? ~u : (u | 0x80000000u);
}
__device__ __forceinline__ float o2f(uint32_t u) {
    return (u & 0x80000000u) ? __uint_as_float(u & 0x7FFFFFFFu)
                             : __uint_as_float(~u);
}

// ---------------- stage 1: score max/argmax + keys ----------------
__global__ void k_score(const float* __restrict__ pred) {
    int q = blockIdx.x * blockDim.x + threadIdx.x;   // group of 4 anchors
    int b = blockIdx.y;
    const int Q = AA / 4;                            // 2100
    if (q >= Q) return;

    const float4* p4 = (const float4*)pred;
    size_t rowbase = ((size_t)b * NCH + 4) * Q + q;

    float4 best = p4[rowbase];
    int cx = 0, cy = 0, cz = 0, cw = 0;
#pragma unroll 8
    for (int c = 1; c < NCC; c++) {
        float4 v = p4[rowbase + (size_t)c * Q];
        if (v.x > best.x) { best.x = v.x; cx = c; }
        if (v.y > best.y) { best.y = v.y; cy = c; }
        if (v.z > best.z) { best.z = v.z; cz = c; }
        if (v.w > best.w) { best.w = v.w; cw = c; }
    }
    int a0 = q * 4;
    float sc[4] = {best.x, best.y, best.z, best.w};
    int   cl[4] = {cx, cy, cz, cw};
#pragma unroll
    for (int t = 0; t < 4; t++) {
        int a = a0 + t;
        float msc = (sc[t] > 0.25f) ? sc[t] : -1.0f;
        g_keys[b * AA + a] = ((uint64_t)f2o(msc) << 32) | (uint32_t)(~a);
        g_cls[b * AA + a]  = cl[t];
    }
}

// ---------------- stage 2: exact top-1500 (radix select) + bitonic sort ----------------
__global__ void __launch_bounds__(1024) k_topk(const float* __restrict__ pred) {
    __shared__ uint32_t hist[256];
    __shared__ uint64_t sortbuf[SORTN];
    __shared__ uint32_t s_cnt;
    __shared__ int s_dstar, s_above;

    int b = blockIdx.x, tid = threadIdx.x;
    const uint64_t* keys = g_keys + (size_t)b * AA;

    // --- MSB radix select: find T = 1500th largest (keys are all distinct) ---
    uint64_t prefix = 0, T = 0;
    int kRem = KTOP, ncand = AA, cur = 0;
    bool useAll = true;

    for (int pass = 0; pass < 8; pass++) {
        int shift = 56 - 8 * pass;
        if (tid < 256) hist[tid] = 0;
        __syncthreads();
        for (int i = tid; i < ncand; i += 1024) {
            uint32_t item = useAll ? (uint32_t)i : g_cand[cur][b][i];
            uint32_t d = (uint32_t)(keys[item] >> shift) & 0xFFu;
            atomicAdd(&hist[d], 1u);
        }
        __syncthreads();
        if (tid == 0) {
            int cum = 0, ds = 0;
            for (int d = 255; d >= 0; d--) {
                int h = (int)hist[d];
                if (cum + h >= kRem) { ds = d; break; }
                cum += h;
            }
            s_dstar = ds; s_above = cum;
        }
        __syncthreads();
        int ds = s_dstar;
        kRem -= s_above;
        prefix |= ((uint64_t)ds) << shift;
        int bc = (int)hist[ds];
        if (kRem == bc || pass == 7) { T = prefix; break; }
        __syncthreads();
        if (tid == 0) s_cnt = 0;
        __syncthreads();
        for (int i = tid; i < ncand; i += 1024) {
            uint32_t item = useAll ? (uint32_t)i : g_cand[cur][b][i];
            uint32_t d = (uint32_t)(keys[item] >> shift) & 0xFFu;
            if (d == (uint32_t)ds) {
                uint32_t p = atomicAdd(&s_cnt, 1u);
                g_cand[cur ^ 1][b][p] = item;
            }
        }
        __syncthreads();
        ncand = (int)s_cnt; cur ^= 1; useAll = false;
        __syncthreads();
    }

    // --- compact keys >= T into smem, pad with 0 ---
    for (int i = tid; i < SORTN; i += 1024) sortbuf[i] = 0;
    if (tid == 0) s_cnt = 0;
    __syncthreads();
    for (int a = tid; a < AA; a += 1024) {
        uint64_t k = keys[a];
        if (k >= T) {
            uint32_t p = atomicAdd(&s_cnt, 1u);
            if (p < SORTN) sortbuf[p] = k;
        }
    }
    __syncthreads();

    // --- bitonic sort descending, n=2048 ---
    for (int kk = 2; kk <= SORTN; kk <<= 1) {
        for (int j = kk >> 1; j > 0; j >>= 1) {
            for (int t = tid; t < SORTN; t += 1024) {
                int l = t ^ j;
                if (l > t) {
                    uint64_t x = sortbuf[t], y = sortbuf[l];
                    bool desc = ((t & kk) == 0);
                    if (desc ? (x < y) : (x > y)) { sortbuf[t] = y; sortbuf[l] = x; }
                }
            }
            __syncthreads();
        }
    }

    // --- emit per-rank data + validity bitmap ---
    const float* pb = pred + (size_t)b * NCH * AA;
    const float SC1 = (float)(1.0 / 80.0 / 640.0);   // mult / IMGSZ
    const float MULT = (float)(1.0 / 80.0);
    for (int rr = 0; rr < 2; rr++) {
        int r = tid + rr * 1024;
        bool inr = r < TPAD;
        bool validf = false;
        if (r < KTOP) {
            uint64_t k = sortbuf[r];
            uint32_t hi = (uint32_t)(k >> 32);
            uint32_t a = ~((uint32_t)k);
            float msc = o2f(hi);
            validf = msc > 0.25f;
            int cls = g_cls[b * AA + a];
            float bx0 = pb[(size_t)0 * AA + a];
            float bx1 = pb[(size_t)1 * AA + a];
            float bx2 = pb[(size_t)2 * AA + a];
            float bx3 = pb[(size_t)3 * AA + a];
            int o = b * TPAD + r;
            g_selbox[o] = make_float4(bx0, bx1, bx2, bx3);
            float off = (float)cls * MULT;
            g_nmsbox[o] = make_float4(bx0 * SC1 + off, bx1 * SC1 + off,
                                      bx2 * SC1 + off, bx3 * SC1 + off);
            g_selscore[o] = msc;
            g_selcls[o] = (float)cls;
        }
        uint32_t vb = __ballot_sync(0xFFFFFFFFu, validf);
        if ((tid & 31) == 0 && inr) g_validbits[b * NWP + (r >> 5)] = vb;
    }
    if (tid < NWP) g_rownz[b * NWP + tid] = 0;       // reset for mask kernel
}

// ---------------- stage 3: suppression bitmask ----------------
__global__ void k_mask() {
    __shared__ float4 sbox[KTOP];
    int b = blockIdx.y;
    int tid = threadIdx.x, warp = tid >> 5, lane = tid & 31;
    const float4* nb = g_nmsbox + (size_t)b * TPAD;
    for (int i = tid; i < KTOP; i += 256) sbox[i] = nb[i];
    __syncthreads();

    int r = blockIdx.x * 8 + warp;
    if (r >= KTOP) return;
    float4 a = sbox[r];
    float areaA = (a.z - a.x) * (a.w - a.y);
    uint32_t* row = g_mask + ((size_t)(b * KTOP + r)) * NWP;
    uint32_t any = 0;
    for (int w = 0; w < NW; w++) {
        int j = w * 32 + lane;
        bool bit = false;
        if (j < KTOP && j > r) {
            float4 bb = sbox[j];
            float lx = fmaxf(a.x, bb.x), ly = fmaxf(a.y, bb.y);
            float rx = fminf(a.z, bb.z), ry = fminf(a.w, bb.w);
            float inter = fmaxf(rx - lx, 0.0f) * fmaxf(ry - ly, 0.0f);
            float areaB = (bb.z - bb.x) * (bb.w - bb.y);
            float iou = inter / (areaA + areaB - inter + 1e-7f);
            bit = iou > 0.45f;
        }
        uint32_t word = __ballot_sync(0xFFFFFFFFu, bit);
        if (lane == 0) row[w] = word;
        any |= word;
    }
    if (lane == 0 && any)
        atomicOr(&g_rownz[b * NWP + (r >> 5)], 1u << (r & 31));
}

// ---------------- stage 4: sequential greedy scan + output ----------------
__global__ void k_scan(float* __restrict__ out) {
    __shared__ uint32_t suppS[NWP], validS[NWP], rownzS[NWP], keepS[NWP], wpre[NWP];
    int b = blockIdx.x, lane = threadIdx.x;      // 32 threads

    for (int t = lane; t < NWP; t += 32) {
        suppS[t] = 0;
        validS[t] = g_validbits[b * NWP + t];
        rownzS[t] = g_rownz[b * NWP + t];
    }
    float* ob = out + (size_t)b * (MAXDET * 6);
    for (int i = lane; i < MAXDET * 6; i += 32) ob[i] = 0.0f;
    __syncwarp();

    const uint32_t* mbase = g_mask + (size_t)b * KTOP * NWP;
    int curw = -1;
    uint32_t sS = 0, sV = 0, sR = 0;
    for (int i = 0; i < KTOP; i++) {
        int w = i >> 5;
        if (w != curw) { curw = w; sS = suppS[w]; sV = validS[w]; sR = rownzS[w]; }
        uint32_t bit = 1u << (i & 31);
        if (!(sS & bit) && (sV & bit) && (sR & bit)) {
            const uint32_t* row = mbase + (size_t)i * NWP;
            suppS[lane] |= row[lane];
            if (lane < NW - 32) suppS[32 + lane] |= row[32 + lane];
            __syncwarp();
            sS = suppS[w];
        }
    }
    __syncwarp();

    // keep = ~supp & valid; build rank prefix, scatter dets
    keepS[lane] = (~suppS[lane]) & validS[lane];
    if (lane < 16) {
        int t = 32 + lane;
        keepS[t] = (t < NW) ? ((~suppS[t]) & validS[t]) : 0u;
    }
    __syncwarp();
    if (lane == 0) {
        uint32_t s = 0;
        for (int w = 0; w < NWP; w++) { wpre[w] = s; s += __popc(keepS[w]); }
    }
    __syncwarp();
    for (int r = lane; r < KTOP; r += 32) {
        int w = r >> 5;
        uint32_t word = keepS[w];
        uint32_t bit = 1u << (r & 31);
        if (word & bit) {
            uint32_t rank = wpre[w] + __popc(word & (bit - 1u));
            if (rank < MAXDET) {
                float4 bx = g_selbox[b * TPAD + r];
                float* o = ob + rank * 6;
                o[0] = bx.x; o[1] = bx.y; o[2] = bx.z; o[3] = bx.w;
                o[4] = g_selscore[b * TPAD + r];
                o[5] = g_selcls[b * TPAD + r];
            }
        }
    }
}

// ---------------- launch ----------------
extern "C" void kernel_launch(void* const* d_in, const int* in_sizes, int n_in,
                              void* d_out, int out_size) {
    const float* pred = (const float*)d_in[0];
    float* out = (float*)d_out;
    k_score<<<dim3((AA / 4 + 255) / 256, BB), 256>>>(pred);
    k_topk<<<BB, 1024>>>(pred);
    k_mask<<<dim3((KTOP + 7) / 8, BB), 256>>>();
    k_scan<<<BB, 32>>>(out);
}

// round 2
// speedup vs baseline: 2.0955x; 2.0955x over previous
#include <cuda_runtime.h>
#include <cstdint>

#define BB 32
#define AA 8400
#define NCH 84
#define NCC 80
#define KTOP 1500
#define TPAD 1536
#define SORTN 2048
#define MAXDET 300
#define NW 47
#define NWP 48

// ---------------- device scratch (static, allocation-free) ----------------
__device__ uint64_t g_keys[BB * AA];                 // sort keys (score|~idx)
__device__ int      g_cls[BB * AA];                  // argmax class per anchor
__device__ uint32_t g_cand[2][BB][AA];               // radix-select candidate lists
__device__ float4   g_selbox[BB * TPAD];             // original boxes of top-k
__device__ float4   g_nmsbox[BB * TPAD];             // class-offset scaled boxes
__device__ float    g_selscore[BB * TPAD];
__device__ float    g_selcls[BB * TPAD];
__device__ uint32_t g_validbits[BB * NWP];
__device__ uint8_t  g_keepB[BB * TPAD];

// orderable float -> uint (monotonic)
__device__ __forceinline__ uint32_t f2o(float f) {
    uint32_t u = __float_as_uint(f);
    return (u & 0x80000000u) ? ~u : (u | 0x80000000u);
}
__device__ __forceinline__ float o2f(uint32_t u) {
    return (u & 0x80000000u) ? __uint_as_float(u & 0x7FFFFFFFu)
                             : __uint_as_float(~u);
}

// ---------------- stage 1: score max/argmax + keys ----------------
__global__ void k_score(const float* __restrict__ pred) {
    int q = blockIdx.x * blockDim.x + threadIdx.x;   // group of 4 anchors
    int b = blockIdx.y;
    const int Q = AA / 4;                            // 2100
    if (q >= Q) return;

    const float4* p4 = (const float4*)pred;
    size_t rowbase = ((size_t)b * NCH + 4) * Q + q;

    float4 best = p4[rowbase];
    int cx = 0, cy = 0, cz = 0, cw = 0;
#pragma unroll 8
    for (int c = 1; c < NCC; c++) {
        float4 v = p4[rowbase + (size_t)c * Q];
        if (v.x > best.x) { best.x = v.x; cx = c; }
        if (v.y > best.y) { best.y = v.y; cy = c; }
        if (v.z > best.z) { best.z = v.z; cz = c; }
        if (v.w > best.w) { best.w = v.w; cw = c; }
    }
    int a0 = q * 4;
    float sc[4] = {best.x, best.y, best.z, best.w};
    int   cl[4] = {cx, cy, cz, cw};
#pragma unroll
    for (int t = 0; t < 4; t++) {
        int a = a0 + t;
        float msc = (sc[t] > 0.25f) ? sc[t] : -1.0f;
        g_keys[b * AA + a] = ((uint64_t)f2o(msc) << 32) | (uint32_t)(~a);
        g_cls[b * AA + a]  = cl[t];
    }
}

// ---------------- stage 2: exact top-1500 (radix select) + bitonic sort ----------------
__global__ void __launch_bounds__(1024) k_topk(const float* __restrict__ pred) {
    __shared__ uint32_t hist[256];
    __shared__ uint32_t scanv[256];
    __shared__ uint64_t sortbuf[SORTN];
    __shared__ uint32_t s_cnt;
    __shared__ int s_dstar, s_above;

    int b = blockIdx.x, tid = threadIdx.x;
    const uint64_t* keys = g_keys + (size_t)b * AA;

    // --- MSB radix select: find T = 1500th largest (keys all distinct) ---
    uint64_t prefix = 0, T = 0;
    int kRem = KTOP, ncand = AA, cur = 0;
    bool useAll = true;

    for (int pass = 0; pass < 8; pass++) {
        int shift = 56 - 8 * pass;
        if (tid < 256) hist[tid] = 0;
        __syncthreads();
        for (int i = tid; i < ncand; i += 1024) {
            uint32_t item = useAll ? (uint32_t)i : g_cand[cur][b][i];
            uint32_t d = (uint32_t)(keys[item] >> shift) & 0xFFu;
            atomicAdd(&hist[d], 1u);
        }
        __syncthreads();
        // parallel suffix-sum over 256 digits
        if (tid < 256) scanv[tid] = hist[tid];
        __syncthreads();
        for (int off = 1; off < 256; off <<= 1) {
            uint32_t v = 0;
            if (tid < 256 && tid + off < 256) v = scanv[tid + off];
            __syncthreads();
            if (tid < 256) scanv[tid] += v;
            __syncthreads();
        }
        if (tid < 256) {
            uint32_t S = scanv[tid];
            uint32_t Snext = (tid == 255) ? 0u : scanv[tid + 1];
            if (S >= (uint32_t)kRem && Snext < (uint32_t)kRem) {
                s_dstar = tid; s_above = (int)Snext;
            }
        }
        __syncthreads();
        int ds = s_dstar;
        kRem -= s_above;
        prefix |= ((uint64_t)ds) << shift;
        int bc = (int)hist[ds];
        if (kRem == bc || pass == 7) { T = prefix; break; }
        __syncthreads();
        if (tid == 0) s_cnt = 0;
        __syncthreads();
        for (int i = tid; i < ncand; i += 1024) {
            uint32_t item = useAll ? (uint32_t)i : g_cand[cur][b][i];
            uint32_t d = (uint32_t)(keys[item] >> shift) & 0xFFu;
            if (d == (uint32_t)ds) {
                uint32_t p = atomicAdd(&s_cnt, 1u);
                g_cand[cur ^ 1][b][p] = item;
            }
        }
        __syncthreads();
        ncand = (int)s_cnt; cur ^= 1; useAll = false;
        __syncthreads();
    }

    // --- compact keys >= T into smem, pad with 0 ---
    for (int i = tid; i < SORTN; i += 1024) sortbuf[i] = 0;
    if (tid == 0) s_cnt = 0;
    // zero keep bytes for k_nms
    for (int i = tid; i < TPAD; i += 1024) g_keepB[b * TPAD + i] = 0;
    __syncthreads();
    for (int a = tid; a < AA; a += 1024) {
        uint64_t k = keys[a];
        if (k >= T) {
            uint32_t p = atomicAdd(&s_cnt, 1u);
            if (p < SORTN) sortbuf[p] = k;
        }
    }
    __syncthreads();

    // --- bitonic sort descending, n=2048 ---
    for (int kk = 2; kk <= SORTN; kk <<= 1) {
        for (int j = kk >> 1; j > 0; j >>= 1) {
            for (int t = tid; t < SORTN; t += 1024) {
                int l = t ^ j;
                if (l > t) {
                    uint64_t x = sortbuf[t], y = sortbuf[l];
                    bool desc = ((t & kk) == 0);
                    if (desc ? (x < y) : (x > y)) { sortbuf[t] = y; sortbuf[l] = x; }
                }
            }
            __syncthreads();
        }
    }

    // --- emit per-rank data + validity bitmap ---
    const float* pb = pred + (size_t)b * NCH * AA;
    const float SC1 = (float)(1.0 / 80.0 / 640.0);   // mult / IMGSZ
    const float MULT = (float)(1.0 / 80.0);
    for (int rr = 0; rr < 2; rr++) {
        int r = tid + rr * 1024;
        bool inr = r < TPAD;
        bool validf = false;
        if (r < KTOP) {
            uint64_t k = sortbuf[r];
            uint32_t hi = (uint32_t)(k >> 32);
            uint32_t a = ~((uint32_t)k);
            float msc = o2f(hi);
            validf = msc > 0.25f;
            int cls = g_cls[b * AA + a];
            float bx0 = pb[(size_t)0 * AA + a];
            float bx1 = pb[(size_t)1 * AA + a];
            float bx2 = pb[(size_t)2 * AA + a];
            float bx3 = pb[(size_t)3 * AA + a];
            int o = b * TPAD + r;
            g_selbox[o] = make_float4(bx0, bx1, bx2, bx3);
            float off = (float)cls * MULT;
            g_nmsbox[o] = make_float4(bx0 * SC1 + off, bx1 * SC1 + off,
                                      bx2 * SC1 + off, bx3 * SC1 + off);
            g_selscore[o] = msc;
            g_selcls[o] = (float)cls;
        }
        uint32_t vb = __ballot_sync(0xFFFFFFFFu, validf);
        if ((tid & 31) == 0 && inr) g_validbits[b * NWP + (r >> 5)] = vb;
    }
}

// ---------------- stage 3: per-(image,class) warp NMS ----------------
// Cross-class IoU is structurally 0 (class offset = 1/80 >= max scaled coord),
// so the global greedy NMS decomposes exactly into per-class chains.
__global__ void k_nms() {
    __shared__ uint16_t slist[8][TPAD];
    __shared__ uint32_t ssupp[8][NWP];
    int b = blockIdx.y;
    int warp = threadIdx.x >> 5, lane = threadIdx.x & 31;
    int c = blockIdx.x * 8 + warp;
    if (c >= NCC) return;
    float cf = (float)c;

    // build rank-ordered list of candidates of class c
    int cnt = 0;
    for (int w = 0; w < NW; w++) {
        int r = w * 32 + lane;
        bool m = false;
        uint32_t vw = g_validbits[b * NWP + w];
        if (r < KTOP && ((vw >> lane) & 1u))
            m = (g_selcls[b * TPAD + r] == cf);
        uint32_t bal = __ballot_sync(0xFFFFFFFFu, m);
        if (m) slist[warp][cnt + __popc(bal & ((1u << lane) - 1u))] = (uint16_t)r;
        cnt += __popc(bal);
    }
    int n = cnt;
    if (n == 0) return;

    if (n <= 32) {
        // register-resident greedy NMS: shfl box broadcast + ballot suppression
        float4 mb = make_float4(0.f, 0.f, 0.f, 0.f);
        int myr = -1;
        if (lane < n) { myr = slist[warp][lane]; mb = g_nmsbox[b * TPAD + myr]; }
        float areaM = (mb.z - mb.x) * (mb.w - mb.y);
        uint32_t supp = 0;
        for (int i = 0; i < n; i++) {
            if ((supp >> i) & 1u) continue;
            float ax = __shfl_sync(0xFFFFFFFFu, mb.x, i);
            float ay = __shfl_sync(0xFFFFFFFFu, mb.y, i);
            float az = __shfl_sync(0xFFFFFFFFu, mb.z, i);
            float aw = __shfl_sync(0xFFFFFFFFu, mb.w, i);
            float areaA = (az - ax) * (aw - ay);
            float lx = fmaxf(ax, mb.x), ly = fmaxf(ay, mb.y);
            float rx = fminf(az, mb.z), ry = fminf(aw, mb.w);
            float inter = fmaxf(rx - lx, 0.f) * fmaxf(ry - ly, 0.f);
            float iou = inter / (areaA + areaM - inter + 1e-7f);
            bool sbit = (lane > i) && (lane < n) && (iou > 0.45f);
            supp |= __ballot_sync(0xFFFFFFFFu, sbit);
        }
        if (lane < n && !((supp >> lane) & 1u)) g_keepB[b * TPAD + myr] = 1;
    } else {
        // general fallback (n > 32): smem supp words, chunked ballots
        int words = (n + 31) >> 5;
        for (int w = lane; w < words; w += 32) ssupp[warp][w] = 0;
        __syncwarp();
        for (int i = 0; i < n; i++) {
            if ((ssupp[warp][i >> 5] >> (i & 31)) & 1u) continue;
            float4 a = g_nmsbox[b * TPAD + slist[warp][i]];
            float areaA = (a.z - a.x) * (a.w - a.y);
            for (int w = i >> 5; w < words; w++) {
                int j = w * 32 + lane;
                bool sbit = false;
                if (j > i && j < n) {
                    float4 bb = g_nmsbox[b * TPAD + slist[warp][j]];
                    float areaB = (bb.z - bb.x) * (bb.w - bb.y);
                    float lx = fmaxf(a.x, bb.x), ly = fmaxf(a.y, bb.y);
                    float rx = fminf(a.z, bb.z), ry = fminf(a.w, bb.w);
                    float inter = fmaxf(rx - lx, 0.f) * fmaxf(ry - ly, 0.f);
                    float iou = inter / (areaA + areaB - inter + 1e-7f);
                    sbit = iou > 0.45f;
                }
                uint32_t bal = __ballot_sync(0xFFFFFFFFu, sbit);
                if (lane == 0 && bal) ssupp[warp][w] |= bal;
                __syncwarp();
            }
        }
        for (int j = lane; j < n; j += 32)
            if (!((ssupp[warp][j >> 5] >> (j & 31)) & 1u))
                g_keepB[b * TPAD + slist[warp][j]] = 1;
    }
}

// ---------------- stage 4: rank compaction + output ----------------
__global__ void k_out(float* __restrict__ out) {
    __shared__ uint32_t keepw[NWP], wpre[NWP];
    int b = blockIdx.x, lane = threadIdx.x;      // 32 threads

    // zero output block first (harness poisons it)
    float* ob = out + (size_t)b * (MAXDET * 6);
    for (int i = lane; i < MAXDET * 6; i += 32) ob[i] = 0.0f;

    // gather keep bits into words (lane->consecutive rank within 32-group)
    for (int w = 0; w < NWP; w++) {
        int r = w * 32 + lane;
        bool k = (r < KTOP) && (g_keepB[b * TPAD + r] != 0);
        uint32_t word = __ballot_sync(0xFFFFFFFFu, k);
        if (lane == 0) keepw[w] = word;
    }
    __syncwarp();
    if (lane == 0) {
        uint32_t s = 0;
        for (int w = 0; w < NWP; w++) { wpre[w] = s; s += __popc(keepw[w]); }
    }
    __syncwarp();
    for (int r = lane; r < KTOP; r += 32) {
        int w = r >> 5;
        uint32_t word = keepw[w];
        uint32_t bit = 1u << (r & 31);
        if (word & bit) {
            uint32_t rank = wpre[w] + __popc(word & (bit - 1u));
            if (rank < MAXDET) {
                float4 bx = g_selbox[b * TPAD + r];
                float* o = ob + rank * 6;
                o[0] = bx.x; o[1] = bx.y; o[2] = bx.z; o[3] = bx.w;
                o[4] = g_selscore[b * TPAD + r];
                o[5] = g_selcls[b * TPAD + r];
            }
        }
    }
}

// ---------------- launch ----------------
extern "C" void kernel_launch(void* const* d_in, const int* in_sizes, int n_in,
                              void* d_out, int out_size) {
    const float* pred = (const float*)d_in[0];
    float* out = (float*)d_out;
    k_score<<<dim3((AA / 4 + 255) / 256, BB), 256>>>(pred);
    k_topk<<<BB, 1024>>>(pred);
    k_nms<<<dim3((NCC + 7) / 8, BB), 256>>>();
    k_out<<<BB, 32>>>(out);
}

// round 3
// speedup vs baseline: 2.6787x; 1.2783x over previous
#include <cuda_runtime.h>
#include <cstdint>

#define BB 32
#define AA 8400
#define NCH 84
#define NCC 80
#define KTOP 1500
#define TPAD 1536
#define SORTN 2048
#define MAXDET 300
#define NW 47
#define NWP 48

// ---------------- device scratch (static, allocation-free) ----------------
__device__ uint64_t g_keys[BB * AA];
__device__ int      g_cls[BB * AA];
__device__ uint32_t g_cand[2][BB][AA];
__device__ float4   g_selbox[BB * TPAD];
__device__ float4   g_nmsbox[BB * TPAD];
__device__ float    g_selscore[BB * TPAD];
__device__ float    g_selcls[BB * TPAD];
__device__ uint8_t  g_clsSel[BB * TPAD];
__device__ uint32_t g_validbits[BB * NWP];
__device__ uint8_t  g_keepB[BB * TPAD];

__device__ __forceinline__ uint32_t f2o(float f) {
    uint32_t u = __float_as_uint(f);
    return (u & 0x80000000u) ? ~u : (u | 0x80000000u);
}
__device__ __forceinline__ float o2f(uint32_t u) {
    return (u & 0x80000000u) ? __uint_as_float(u & 0x7FFFFFFFu)
                             : __uint_as_float(~u);
}

// ---------------- stage 1: score max/argmax + keys ----------------
__global__ void k_score(const float* __restrict__ pred) {
    int q = blockIdx.x * blockDim.x + threadIdx.x;   // group of 4 anchors
    int b = blockIdx.y;
    const int Q = AA / 4;
    if (q >= Q) return;

    const float4* p4 = (const float4*)pred;
    size_t rowbase = ((size_t)b * NCH + 4) * Q + q;

    float4 best = p4[rowbase];
    int cx = 0, cy = 0, cz = 0, cw = 0;
#pragma unroll 8
    for (int c = 1; c < NCC; c++) {
        float4 v = p4[rowbase + (size_t)c * Q];
        if (v.x > best.x) { best.x = v.x; cx = c; }
        if (v.y > best.y) { best.y = v.y; cy = c; }
        if (v.z > best.z) { best.z = v.z; cz = c; }
        if (v.w > best.w) { best.w = v.w; cw = c; }
    }
    int a0 = q * 4;
    float sc[4] = {best.x, best.y, best.z, best.w};
    int   cl[4] = {cx, cy, cz, cw};
#pragma unroll
    for (int t = 0; t < 4; t++) {
        int a = a0 + t;
        float msc = (sc[t] > 0.25f) ? sc[t] : -1.0f;
        g_keys[b * AA + a] = ((uint64_t)f2o(msc) << 32) | (uint32_t)(~a);
        g_cls[b * AA + a]  = cl[t];
    }
}

// ---------------- stage 2: radix prune (early exit) + bitonic sort ----------------
__global__ void __launch_bounds__(1024) k_topk(const float* __restrict__ pred) {
    __shared__ uint32_t hist[256];
    __shared__ uint64_t sortbuf[SORTN];
    __shared__ uint32_t s_cnt;
    __shared__ int s_dstar, s_above;

    int b = blockIdx.x, tid = threadIdx.x;
    const uint64_t* keys = g_keys + (size_t)b * AA;

    // Find threshold T such that 1500 <= |{k >= T}| <= 2048 (sort finishes the select)
    uint64_t prefix = 0, T = 0;
    int kRem = KTOP, ncand = AA, cur = 0;
    bool useAll = true;

    for (int pass = 0; pass < 8; pass++) {
        int shift = 56 - 8 * pass;
        if (tid < 256) hist[tid] = 0;
        __syncthreads();
        for (int i = tid; i < ncand; i += 1024) {
            uint32_t item = useAll ? (uint32_t)i : g_cand[cur][b][i];
            uint32_t d = (uint32_t)(keys[item] >> shift) & 0xFFu;
            atomicAdd(&hist[d], 1u);
        }
        __syncthreads();
        // single-warp digit select (descending digits)
        if (tid < 32) {
            int lane = tid;
            int base = 255 - lane * 8;
            uint32_t h[8]; uint32_t sum = 0;
#pragma unroll
            for (int k = 0; k < 8; k++) { h[k] = hist[base - k]; sum += h[k]; }
            uint32_t pre = sum;
#pragma unroll
            for (int off = 1; off < 32; off <<= 1) {
                uint32_t v = __shfl_up_sync(0xFFFFFFFFu, pre, off);
                if (lane >= off) pre += v;
            }
            uint32_t cum = pre - sum;     // count in digits strictly above lane's block
#pragma unroll
            for (int k = 0; k < 8; k++) {
                int d = base - k;
                if (cum < (uint32_t)kRem && cum + h[k] >= (uint32_t)kRem) {
                    s_dstar = d; s_above = (int)cum;
                }
                cum += h[k];
            }
        }
        __syncthreads();
        int ds = s_dstar;
        kRem -= s_above;
        prefix |= ((uint64_t)ds) << shift;
        int bc = (int)hist[ds];
        // early exit: selected-so-far + tie bucket fits in sort buffer
        if ((KTOP - kRem) + bc <= SORTN || pass == 7) { T = prefix; break; }
        __syncthreads();
        if (tid == 0) s_cnt = 0;
        __syncthreads();
        for (int i = tid; i < ncand; i += 1024) {
            uint32_t item = useAll ? (uint32_t)i : g_cand[cur][b][i];
            uint32_t d = (uint32_t)(keys[item] >> shift) & 0xFFu;
            if (d == (uint32_t)ds) {
                uint32_t p = atomicAdd(&s_cnt, 1u);
                g_cand[cur ^ 1][b][p] = item;
            }
        }
        __syncthreads();
        ncand = (int)s_cnt; cur ^= 1; useAll = false;
        __syncthreads();
    }

    // compact keys >= T into smem (count <= 2048 guaranteed), pad with 0
    for (int i = tid; i < SORTN; i += 1024) sortbuf[i] = 0;
    if (tid == 0) s_cnt = 0;
    for (int i = tid; i < TPAD; i += 1024) g_keepB[b * TPAD + i] = 0;
    __syncthreads();
    for (int a = tid; a < AA; a += 1024) {
        uint64_t k = keys[a];
        if (k >= T) {
            uint32_t p = atomicAdd(&s_cnt, 1u);
            sortbuf[p] = k;
        }
    }
    __syncthreads();

    // bitonic sort descending, n=2048
    for (int kk = 2; kk <= SORTN; kk <<= 1) {
        for (int j = kk >> 1; j > 0; j >>= 1) {
            for (int t = tid; t < SORTN; t += 1024) {
                int l = t ^ j;
                if (l > t) {
                    uint64_t x = sortbuf[t], y = sortbuf[l];
                    bool desc = ((t & kk) == 0);
                    if (desc ? (x < y) : (x > y)) { sortbuf[t] = y; sortbuf[l] = x; }
                }
            }
            __syncthreads();
        }
    }

    // emit per-rank data + validity bitmap
    const float* pb = pred + (size_t)b * NCH * AA;
    const float SC1 = (float)(1.0 / 80.0 / 640.0);
    const float MULT = (float)(1.0 / 80.0);
    for (int rr = 0; rr < 2; rr++) {
        int r = tid + rr * 1024;
        bool inr = r < TPAD;
        bool validf = false;
        if (r < KTOP) {
            uint64_t k = sortbuf[r];
            uint32_t hi = (uint32_t)(k >> 32);
            uint32_t a = ~((uint32_t)k);
            float msc = o2f(hi);
            validf = msc > 0.25f;
            int cls = g_cls[b * AA + a];
            float bx0 = pb[(size_t)0 * AA + a];
            float bx1 = pb[(size_t)1 * AA + a];
            float bx2 = pb[(size_t)2 * AA + a];
            float bx3 = pb[(size_t)3 * AA + a];
            int o = b * TPAD + r;
            g_selbox[o] = make_float4(bx0, bx1, bx2, bx3);
            float off = (float)cls * MULT;
            g_nmsbox[o] = make_float4(bx0 * SC1 + off, bx1 * SC1 + off,
                                      bx2 * SC1 + off, bx3 * SC1 + off);
            g_selscore[o] = msc;
            g_selcls[o] = (float)cls;
            g_clsSel[o] = (uint8_t)cls;
        } else if (inr) {
            g_clsSel[b * TPAD + r] = 0xFF;
        }
        uint32_t vb = __ballot_sync(0xFFFFFFFFu, validf);
        if ((tid & 31) == 0 && inr) g_validbits[b * NWP + (r >> 5)] = vb;
    }
}

// ---------------- stage 3: per-(image,class) warp NMS, smem-staged ----------------
__global__ void k_nms() {
    __shared__ uint8_t  sCls[TPAD];
    __shared__ uint32_t sValid[NWP];
    __shared__ uint16_t slist[8][TPAD];
    __shared__ uint32_t ssupp[8][NWP];
    int b = blockIdx.y;
    int tid = threadIdx.x, warp = tid >> 5, lane = tid & 31;
    int c = blockIdx.x * 8 + warp;          // 10 blocks x 8 warps = 80 classes exactly
    float cf = (float)c;

    // cooperative prefetch of class bytes + valid bits
    const uint32_t* gc4 = (const uint32_t*)(g_clsSel + b * TPAD);
    uint32_t* sc4 = (uint32_t*)sCls;
    for (int i = tid; i < TPAD / 4; i += 256) sc4[i] = gc4[i];
    if (tid < NWP) sValid[tid] = g_validbits[b * NWP + tid];
    __syncthreads();

    // build rank-ordered candidate list for class c (LDS-latency ballots)
    int cnt = 0;
    for (int w = 0; w < NW; w++) {
        int r = w * 32 + lane;
        bool m = (r < KTOP) && ((sValid[w] >> lane) & 1u) && (sCls[r] == (uint8_t)c);
        uint32_t bal = __ballot_sync(0xFFFFFFFFu, m);
        if (m) slist[warp][cnt + __popc(bal & ((1u << lane) - 1u))] = (uint16_t)r;
        cnt += __popc(bal);
    }
    int n = cnt;
    if (n == 0) return;

    if (n <= 32) {
        float4 mb = make_float4(0.f, 0.f, 0.f, 0.f);
        int myr = -1;
        if (lane < n) { myr = slist[warp][lane]; mb = g_nmsbox[b * TPAD + myr]; }
        float areaM = (mb.z - mb.x) * (mb.w - mb.y);
        uint32_t supp = 0;
        for (int i = 0; i < n; i++) {
            if ((supp >> i) & 1u) continue;
            float ax = __shfl_sync(0xFFFFFFFFu, mb.x, i);
            float ay = __shfl_sync(0xFFFFFFFFu, mb.y, i);
            float az = __shfl_sync(0xFFFFFFFFu, mb.z, i);
            float aw = __shfl_sync(0xFFFFFFFFu, mb.w, i);
            float areaA = (az - ax) * (aw - ay);
            float lx = fmaxf(ax, mb.x), ly = fmaxf(ay, mb.y);
            float rx = fminf(az, mb.z), ry = fminf(aw, mb.w);
            float inter = fmaxf(rx - lx, 0.f) * fmaxf(ry - ly, 0.f);
            float iou = inter / (areaA + areaM - inter + 1e-7f);
            bool sbit = (lane > i) && (lane < n) && (iou > 0.45f);
            supp |= __ballot_sync(0xFFFFFFFFu, sbit);
        }
        if (lane < n && !((supp >> lane) & 1u)) g_keepB[b * TPAD + myr] = 1;
    } else {
        int words = (n + 31) >> 5;
        for (int w = lane; w < words; w += 32) ssupp[warp][w] = 0;
        __syncwarp();
        for (int i = 0; i < n; i++) {
            if ((ssupp[warp][i >> 5] >> (i & 31)) & 1u) continue;
            float4 a = g_nmsbox[b * TPAD + slist[warp][i]];
            float areaA = (a.z - a.x) * (a.w - a.y);
            for (int w = i >> 5; w < words; w++) {
                int j = w * 32 + lane;
                bool sbit = false;
                if (j > i && j < n) {
                    float4 bb = g_nmsbox[b * TPAD + slist[warp][j]];
                    float areaB = (bb.z - bb.x) * (bb.w - bb.y);
                    float lx = fmaxf(a.x, bb.x), ly = fmaxf(a.y, bb.y);
                    float rx = fminf(a.z, bb.z), ry = fminf(a.w, bb.w);
                    float inter = fmaxf(rx - lx, 0.f) * fmaxf(ry - ly, 0.f);
                    float iou = inter / (areaA + areaB - inter + 1e-7f);
                    sbit = iou > 0.45f;
                }
                uint32_t bal = __ballot_sync(0xFFFFFFFFu, sbit);
                if (lane == 0 && bal) ssupp[warp][w] |= bal;
                __syncwarp();
            }
        }
        for (int j = lane; j < n; j += 32)
            if (!((ssupp[warp][j >> 5] >> (j & 31)) & 1u))
                g_keepB[b * TPAD + slist[warp][j]] = 1;
    }
}

// ---------------- stage 4: parallel rank compaction + output ----------------
__global__ void __launch_bounds__(256) k_out(float* __restrict__ out) {
    __shared__ uint32_t keepw[NWP], wpre[NWP];
    int b = blockIdx.x, tid = threadIdx.x;
    int warp = tid >> 5, lane = tid & 31;

    float* ob = out + (size_t)b * (MAXDET * 6);
    for (int i = tid; i < MAXDET * 6; i += 256) ob[i] = 0.0f;

    // 8 warps x 6 words each; prefetch keep bytes (MLP=6), then ballots
    uint8_t kb[6];
#pragma unroll
    for (int s = 0; s < 6; s++) {
        int w = warp * 6 + s;
        kb[s] = g_keepB[b * TPAD + w * 32 + lane];
    }
#pragma unroll
    for (int s = 0; s < 6; s++) {
        uint32_t word = __ballot_sync(0xFFFFFFFFu, kb[s] != 0);
        if (lane == 0) keepw[warp * 6 + s] = word;
    }
    __syncthreads();
    if (tid == 0) {
        uint32_t s = 0;
        for (int w = 0; w < NWP; w++) { wpre[w] = s; s += __popc(keepw[w]); }
    }
    __syncthreads();
    for (int r = tid; r < KTOP; r += 256) {
        int w = r >> 5;
        uint32_t word = keepw[w];
        uint32_t bit = 1u << (r & 31);
        if (word & bit) {
            uint32_t rank = wpre[w] + __popc(word & (bit - 1u));
            if (rank < MAXDET) {
                float4 bx = g_selbox[b * TPAD + r];
                float* o = ob + rank * 6;
                o[0] = bx.x; o[1] = bx.y; o[2] = bx.z; o[3] = bx.w;
                o[4] = g_selscore[b * TPAD + r];
                o[5] = g_selcls[b * TPAD + r];
            }
        }
    }
}

// ---------------- launch ----------------
extern "C" void kernel_launch(void* const* d_in, const int* in_sizes, int n_in,
                              void* d_out, int out_size) {
    const float* pred = (const float*)d_in[0];
    float* out = (float*)d_out;
    k_score<<<dim3((AA / 4 + 255) / 256, BB), 256>>>(pred);
    k_topk<<<BB, 1024>>>(pred);
    k_nms<<<dim3(10, BB), 256>>>();
    k_out<<<BB, 256>>>(out);
}